// round 8
// baseline (speedup 1.0000x reference)
#include <cuda_runtime.h>
#include <math_constants.h>

// Morphological opening (10x10 min then 10x10 max, SAME pad lo=4/hi=5),
// NHWC [16,512,512,8] f32, split into two symmetric passes through a
// transposed global scratch:
//   K1 erosion:  V-min (fused w/ coalesced load) -> smem -> H-min
//                -> scratch S[b][x][y][ch] (transposed, coalesced-ish)
//   K2 dilation: max-along-x (fused w/ coalesced load of S; off-image = -inf,
//                which IS the dilation pad) -> smem -> max-along-y -> out.
// Each kernel: one smem buffer (77.1KB -> 3 blocks/SM), one barrier.

#define H_  512
#define W_  512
#define NT  256

#define NCF  146          // (64+9)*2 fused (coord, float4-half) columns
#define NEP  33           // padded e-stride (conflict-free: 132 words -> bank 4l)
#define SMEM_F4 (NCF * NEP)          // 4818
#define SMEM_BYTES (SMEM_F4 * 16)    // 77088

// Transposed eroded scratch: S[b][x][y][h], f4 units. 134MB static.
__device__ float4 g_scratch[16 * 512 * 512 * 2];

__device__ __forceinline__ float4 min4(float4 a, float4 b) {
    return make_float4(fminf(a.x,b.x), fminf(a.y,b.y), fminf(a.z,b.z), fminf(a.w,b.w));
}
__device__ __forceinline__ float4 max4(float4 a, float4 b) {
    return make_float4(fmaxf(a.x,b.x), fmaxf(a.y,b.y), fmaxf(a.z,b.z), fmaxf(a.w,b.w));
}

// ============================ K1: erosion =================================
// Block: 32 y-outputs x 64 x-outputs x 8 channels.
__global__ __launch_bounds__(NT, 3)
void erode_kernel(const float4* __restrict__ in4) {
    extern __shared__ float4 B[];     // B[cF][e]: cF in [0,146), e in [0,32), stride 33
    const int b   = blockIdx.z;
    const int gy0 = blockIdx.y * 32;
    const int gx0 = blockIdx.x * 64;
    const int tid = threadIdx.x;
    const float4 INF4 = make_float4(CUDART_INF_F, CUDART_INF_F, CUDART_INF_F, CUDART_INF_F);

    const size_t inBase = (size_t)b * H_ * W_ * 2;

    // ---- Stage 1: vertical min fused with coalesced load. 146 x 4 = 584. ----
    // B[cF][e] = min over input rows gy0+e-4 .. gy0+e+5 at x = gx0 + (cF>>1) - 4.
    #pragma unroll 1
    for (int i = tid; i < NCF * 4; i += NT) {
        int cF = i % NCF, seg = i / NCF;
        int e0 = seg * 9;
        int n  = (seg == 3) ? 5 : 9;             // 9+9+9+5 = 32
        int gx = gx0 + (cF >> 1) - 4;
        bool colOK = ((unsigned)gx < W_);
        const float4* src = in4 + inBase + (size_t)(gx0 - 4) * 2 + cF;  // + y*1024
        int yBase = gy0 + e0 - 4;

        float4 x[10];
        #pragma unroll
        for (int t = 0; t < 10; t++) {
            int gy = yBase + t;
            x[t] = (colOK && (unsigned)gy < H_) ? src[(size_t)gy * (W_ * 2)] : INF4;
        }
        #pragma unroll
        for (int j = 8; j >= 0; j--) x[j] = min4(x[j], x[j+1]);
        float4 pr = x[9];
        float4* q = B + cF * NEP + e0;
        q[0] = x[0];
        #pragma unroll
        for (int j = 1; j < 9; j++) {
            if (j >= n) break;
            int gy = yBase + 9 + j;
            float4 xn = (colOK && (unsigned)gy < H_) ? src[(size_t)gy * (W_ * 2)] : INF4;
            pr = min4(pr, xn);
            q[j] = min4(x[j], pr);
        }
    }
    __syncthreads();

    // ---- Stage 2: horizontal min, write transposed scratch. 512 tasks. ----
    // Output x = gx0 + c0 + j (64 per block: 7 segs of 9 + 1), y = gy0 + e.
    #pragma unroll 1
    for (int i = tid; i < 512; i += NT) {
        int e   = i & 31;
        int t2  = i >> 5;              // 0..15
        int h   = t2 & 1;
        int seg = t2 >> 1;             // 0..7
        int c0  = seg * 9;
        int n   = (seg == 7) ? 1 : 9;
        const float4* p = B + (c0 * 2 + h) * NEP + e;    // x-step = 2*NEP
        float4 x[10];
        #pragma unroll
        for (int t = 0; t < 10; t++) x[t] = p[t * (2 * NEP)];
        #pragma unroll
        for (int j = 8; j >= 0; j--) x[j] = min4(x[j], x[j+1]);
        float4 pr = x[9];
        float4* q = g_scratch + (size_t)b * (H_ * W_ * 2)
                  + ((size_t)(gx0 + c0) * H_ + (gy0 + e)) * 2 + h;
        q[0] = x[0];
        #pragma unroll
        for (int j = 1; j < 9; j++) {
            if (j >= n) break;
            pr = min4(pr, p[(9 + j) * (2 * NEP)]);
            q[(size_t)j * (H_ * 2)] = min4(x[j], pr);
        }
    }
}

// ============================ K2: dilation ================================
// Block: 32 x-outputs x 64 y-outputs x 8 channels. Mirror of K1 on S.
__global__ __launch_bounds__(NT, 3)
void dilate_kernel(float4* __restrict__ out4) {
    extern __shared__ float4 B[];     // B[yF][e]: yF in [0,146), e = x-idx in [0,32)
    const int b   = blockIdx.z;
    const int gx0 = blockIdx.y * 32;
    const int gy0 = blockIdx.x * 64;
    const int tid = threadIdx.x;
    const float4 NINF4 = make_float4(-CUDART_INF_F, -CUDART_INF_F, -CUDART_INF_F, -CUDART_INF_F);

    const size_t sBase = (size_t)b * (H_ * W_ * 2);

    // ---- Stage 1: max along x fused with coalesced load of S. 146x4=584. ----
    // B[yF][e] = max over eroded x = gx0+e-4 .. gx0+e+5 at y = gy0 + (yF>>1) - 4.
    // Off-image (x or y) contributes -inf == dilation SAME padding.
    #pragma unroll 1
    for (int i = tid; i < NCF * 4; i += NT) {
        int yF = i % NCF, seg = i / NCF;
        int e0 = seg * 9;
        int n  = (seg == 3) ? 5 : 9;
        int gy = gy0 + (yF >> 1) - 4;
        bool yOK = ((unsigned)gy < H_);
        const float4* src = g_scratch + sBase + (size_t)(gy0 - 4) * 2 + yF;  // + x*1024
        int xBase = gx0 + e0 - 4;

        float4 x[10];
        #pragma unroll
        for (int t = 0; t < 10; t++) {
            int gx = xBase + t;
            x[t] = (yOK && (unsigned)gx < W_) ? src[(size_t)gx * (H_ * 2)] : NINF4;
        }
        #pragma unroll
        for (int j = 8; j >= 0; j--) x[j] = max4(x[j], x[j+1]);
        float4 pr = x[9];
        float4* q = B + yF * NEP + e0;
        q[0] = x[0];
        #pragma unroll
        for (int j = 1; j < 9; j++) {
            if (j >= n) break;
            int gx = xBase + 9 + j;
            float4 xn = (yOK && (unsigned)gx < W_) ? src[(size_t)gx * (H_ * 2)] : NINF4;
            pr = max4(pr, xn);
            q[j] = max4(x[j], pr);
        }
    }
    __syncthreads();

    // ---- Stage 2: max along y, write output (original layout). 512 tasks. ----
    // Output y = gy0 + c0 + j (64 per block), x = gx0 + e. WEIGHT = 1.0.
    #pragma unroll 1
    for (int i = tid; i < 512; i += NT) {
        int e   = i & 31;
        int t2  = i >> 5;
        int h   = t2 & 1;
        int seg = t2 >> 1;
        int c0  = seg * 9;
        int n   = (seg == 7) ? 1 : 9;
        const float4* p = B + (c0 * 2 + h) * NEP + e;    // y-step = 2*NEP
        float4 x[10];
        #pragma unroll
        for (int t = 0; t < 10; t++) x[t] = p[t * (2 * NEP)];
        #pragma unroll
        for (int j = 8; j >= 0; j--) x[j] = max4(x[j], x[j+1]);
        float4 pr = x[9];
        float4* q = out4 + (size_t)b * (H_ * W_ * 2)
                  + ((size_t)(gy0 + c0) * W_ + (gx0 + e)) * 2 + h;
        q[0] = x[0];
        #pragma unroll
        for (int j = 1; j < 9; j++) {
            if (j >= n) break;
            pr = max4(pr, p[(9 + j) * (2 * NEP)]);
            q[(size_t)j * (W_ * 2)] = max4(x[j], pr);
        }
    }
}

extern "C" void kernel_launch(void* const* d_in, const int* in_sizes, int n_in,
                              void* d_out, int out_size) {
    const float4* in  = (const float4*)d_in[0];
    float4* out = (float4*)d_out;

    cudaFuncSetAttribute(erode_kernel,
                         cudaFuncAttributeMaxDynamicSharedMemorySize, SMEM_BYTES);
    cudaFuncSetAttribute(dilate_kernel,
                         cudaFuncAttributeMaxDynamicSharedMemorySize, SMEM_BYTES);

    dim3 g1(W_ / 64, H_ / 32, 16);   // x-tiles, y-tiles, batch
    dim3 g2(H_ / 64, W_ / 32, 16);   // y-tiles, x-tiles, batch
    erode_kernel <<<g1, NT, SMEM_BYTES>>>(in);
    dilate_kernel<<<g2, NT, SMEM_BYTES>>>(out);
}